// round 13
// baseline (speedup 1.0000x reference)
#include <cuda_runtime.h>
#include <cuda_fp16.h>
#include <cstdint>

// ---------------------------------------------------------------------------
// Attention_37074157699274 — round 12: persistent GEMM CTAs.
// 304 CTAs (2/SM) loop over tiles with ONE continuous 3-stage cp.async ring
// spanning tile boundaries (no per-tile pipeline fill/drain). Tail chunks
// commit empty groups to keep wait_group 1 invariant.
//   K0: x->fp16 ; T1/T2: weights -> [N,K] fp16
//   K1: qkv = xh @ W_qkv ; K2: attn (warp=head, reg softmax) ; K3: out proj
// ---------------------------------------------------------------------------

#define TOKENS   131072
#define GROUPS   4096
#define DIMX     256
#define NQKV     1536
#define INNER    512
#define HEADS    8
#define DH       64
#define ATT_SCALE 0.125f
#define GRIDSZ   304

__device__ __half g_xh  [(size_t)TOKENS * DIMX];
__device__ __half g_qkv [(size_t)TOKENS * NQKV];
__device__ __half g_attn[(size_t)TOKENS * INNER];
__device__ __half g_WqkvT[(size_t)NQKV * DIMX];
__device__ __half g_WoutT[(size_t)DIMX * INNER];

// ------------------------- helpers ------------------------------------------

__device__ __forceinline__ uint32_t pack2h(float x, float y) {
    __half2 h = __halves2half2(__float2half_rn(x), __float2half_rn(y));
    return *reinterpret_cast<uint32_t*>(&h);
}
__device__ __forceinline__ uint32_t smem_u32(const void* p) {
    uint32_t a;
    asm("{ .reg .u64 t; cvta.to.shared.u64 t, %1; cvt.u32.u64 %0, t; }"
        : "=r"(a) : "l"(p));
    return a;
}
__device__ __forceinline__ void cp16(uint32_t saddr, const void* gptr) {
    asm volatile("cp.async.cg.shared.global [%0], [%1], 16;"
                 :: "r"(saddr), "l"(gptr) : "memory");
}
__device__ __forceinline__ void ldsm4(uint32_t r[4], uint32_t addr) {
    asm volatile("ldmatrix.sync.aligned.m8n8.x4.shared.b16 {%0,%1,%2,%3}, [%4];"
                 : "=r"(r[0]), "=r"(r[1]), "=r"(r[2]), "=r"(r[3]) : "r"(addr));
}
__device__ __forceinline__ void ldsm4t(uint32_t r[4], uint32_t addr) {
    asm volatile("ldmatrix.sync.aligned.m8n8.x4.trans.shared.b16 {%0,%1,%2,%3}, [%4];"
                 : "=r"(r[0]), "=r"(r[1]), "=r"(r[2]), "=r"(r[3]) : "r"(addr));
}
__device__ __forceinline__ void mma_f16(float c[4], uint32_t a0, uint32_t a1,
                                        uint32_t a2, uint32_t a3,
                                        uint32_t b0, uint32_t b1) {
    asm volatile(
        "mma.sync.aligned.m16n8k16.row.col.f32.f16.f16.f32 "
        "{%0,%1,%2,%3}, {%4,%5,%6,%7}, {%8,%9}, {%0,%1,%2,%3};\n"
        : "+f"(c[0]), "+f"(c[1]), "+f"(c[2]), "+f"(c[3])
        : "r"(a0), "r"(a1), "r"(a2), "r"(a3), "r"(b0), "r"(b1));
}

// ------------------------- persistent GEMM ----------------------------------
// C[M,N] = A[M,K] @ Bt[N,K]^T (+bias). Tile 128x128, K-chunk 64, 3-stage
// continuous ring, 256 thr = 8 warps 2(M)x4(N), warp tile 64x32, ldmatrix.
// smem rows = 72 halfs (144 B; 144 mod 128 = 16 -> conflict-free ldsm).

#define STRB   144
#define A_BYTES (128 * STRB)              // 18432
#define B_BYTES (128 * STRB)              // 18432
#define STG_BYTES (A_BYTES + B_BYTES)     // 36864
#define NSTG   3
#define GSM_BYTES (NSTG * STG_BYTES)      // 110592

template<typename TC>
__global__ __launch_bounds__(256, 2)
void gemm_h(const __half* __restrict__ A, const __half* __restrict__ Bt,
            TC* __restrict__ C, int K, int N, int nTX, int totalTiles,
            const float* __restrict__ bias)
{
    extern __shared__ __half sh[];
    const uint32_t sb = smem_u32(sh);

    const int t     = threadIdx.x;
    const int lane  = t & 31;
    const int warp  = t >> 5;
    const int warpM = warp & 1;
    const int warpN = warp >> 1;
    const int bid   = blockIdx.x;

    const int NC = K >> 6;                      // chunks of 64 per tile
    // tiles handled by this CTA: bid, bid+GRIDSZ, ...
    const int nMy = (totalTiles - 1 - bid) / GRIDSZ + 1;
    const long totalQ = (long)nMy * NC;
    if (bid >= totalTiles) return;

    // stage chunk q (global index) into slot q%3, one commit per call
    auto stageQ = [&](long q) {
        int i  = (int)(q / NC);
        int kc = (int)(q - (long)i * NC);
        long tIdx = (long)bid + (long)i * GRIDSZ;
        int by = (int)(tIdx / nTX);
        int bx = (int)(tIdx - (long)by * nTX);
        const __half* As = A  + ((size_t)by * 128) * K + kc * 64;
        const __half* Bs = Bt + ((size_t)bx * 128) * K + kc * 64;
        const uint32_t aD = sb + (int)(q % NSTG) * STG_BYTES;
        const uint32_t bD = aD + A_BYTES;
        #pragma unroll
        for (int it = 0; it < 4; it++) {         // A: 1024 16B-granules
            int g = it * 256 + t, r = g >> 3, s = g & 7;
            cp16(aD + r * STRB + s * 16, As + (size_t)r * K + s * 8);
        }
        #pragma unroll
        for (int it = 0; it < 4; it++) {         // B: 1024 granules
            int g = it * 256 + t, r = g >> 3, s = g & 7;
            cp16(bD + r * STRB + s * 16, Bs + (size_t)r * K + s * 8);
        }
        asm volatile("cp.async.commit_group;" ::: "memory");
    };

    float acc[4][4][4];
    #pragma unroll
    for (int mt = 0; mt < 4; mt++)
        #pragma unroll
        for (int nt = 0; nt < 4; nt++)
            #pragma unroll
            for (int i = 0; i < 4; i++) acc[mt][nt][i] = 0.f;

    stageQ(0);
    if (totalQ > 1) stageQ(1);
    else            asm volatile("cp.async.commit_group;" ::: "memory");
    long qc = 2;

    const int lr    = lane & 15;
    const int aKoff = (lane & 16) ? 16 : 0;
    const int bRow  = (lane & 7) + ((lane & 16) ? 8 : 0);
    const int bKoff = (lane & 8) ? 16 : 0;

    size_t rowBase = 0; int colBase = 0;

    for (long q = 0; q < totalQ; q++) {
        int kc = (int)(q % NC);
        if (kc == 0) {                           // new tile: compute-side params
            long tIdx = (long)bid + (q / NC) * GRIDSZ;
            int by = (int)(tIdx / nTX);
            int bx = (int)(tIdx - (long)by * nTX);
            rowBase = (size_t)by * 128;
            colBase = bx * 128;
        }

        asm volatile("cp.async.wait_group 1;" ::: "memory");
        __syncthreads();
        if (qc < totalQ) stageQ(qc);
        else asm volatile("cp.async.commit_group;" ::: "memory");
        qc++;

        const uint32_t aB = sb + (int)(q % NSTG) * STG_BYTES;
        const uint32_t bB = aB + A_BYTES;

        #pragma unroll
        for (int ks = 0; ks < 4; ks++) {
            const int k0b = ks * 32;
            uint32_t a[4][4], b[2][4];
            #pragma unroll
            for (int mt = 0; mt < 4; mt++)
                ldsm4(a[mt], aB + (warpM * 64 + mt * 16 + lr) * STRB + k0b + aKoff);
            #pragma unroll
            for (int np = 0; np < 2; np++)
                ldsm4(b[np], bB + (warpN * 32 + np * 16 + bRow) * STRB + k0b + bKoff);
            #pragma unroll
            for (int nt = 0; nt < 4; nt++) {
                uint32_t b0 = b[nt >> 1][(nt & 1) * 2];
                uint32_t b1 = b[nt >> 1][(nt & 1) * 2 + 1];
                #pragma unroll
                for (int mt = 0; mt < 4; mt++)
                    mma_f16(acc[mt][nt], a[mt][0], a[mt][1], a[mt][2], a[mt][3],
                            b0, b1);
            }
        }

        if (kc == NC - 1) {                      // tile done: epilogue + reset
            #pragma unroll
            for (int mt = 0; mt < 4; mt++) {
                size_t row = rowBase + warpM * 64 + mt * 16 + (lane >> 2);
                #pragma unroll
                for (int nt = 0; nt < 4; nt++) {
                    int col = colBase + warpN * 32 + nt * 8 + 2 * (lane & 3);
                    if constexpr (sizeof(TC) == 2) {
                        __half* cp = (__half*)C;
                        *(uint32_t*)(cp + row * N + col) =
                            pack2h(acc[mt][nt][0], acc[mt][nt][1]);
                        *(uint32_t*)(cp + (row + 8) * N + col) =
                            pack2h(acc[mt][nt][2], acc[mt][nt][3]);
                    } else {
                        float b0 = 0.f, b1 = 0.f;
                        if (bias) { b0 = bias[col]; b1 = bias[col + 1]; }
                        float* cp = (float*)C;
                        *(float2*)(cp + row * N + col) =
                            make_float2(acc[mt][nt][0] + b0, acc[mt][nt][1] + b1);
                        *(float2*)(cp + (row + 8) * N + col) =
                            make_float2(acc[mt][nt][2] + b0, acc[mt][nt][3] + b1);
                    }
                    #pragma unroll
                    for (int i = 0; i < 4; i++) acc[mt][nt][i] = 0.f;
                }
            }
        }
    }
}

// ------------------------- aux kernels --------------------------------------

__global__ void f2h_kernel(const float* __restrict__ in, __half* __restrict__ out,
                           int n4)
{
    int i = blockIdx.x * blockDim.x + threadIdx.x;
    if (i < n4) {
        float4 v = ((const float4*)in)[i];
        ((uint2*)out)[i] = make_uint2(pack2h(v.x, v.y), pack2h(v.z, v.w));
    }
}

__global__ void transpose_h(const float* __restrict__ in, __half* __restrict__ out,
                            int R, int C)
{
    __shared__ float tile[32][33];
    int c0 = blockIdx.x * 32, r0 = blockIdx.y * 32;
    #pragma unroll
    for (int i = threadIdx.y; i < 32; i += 8)
        tile[i][threadIdx.x] = in[(size_t)(r0 + i) * C + c0 + threadIdx.x];
    __syncthreads();
    #pragma unroll
    for (int i = threadIdx.y; i < 32; i += 8)
        out[(size_t)(c0 + i) * R + r0 + threadIdx.x] =
            __float2half_rn(tile[threadIdx.x][i]);
}

// ------------------------- K2: attention, warp = head (round-11 proven) -----

#define ROWH 1544
#define ROWB (ROWH * 2)
#define ASM_BYTES (32 * ROWB)

__global__ __launch_bounds__(256)
void attn_core(const __half* __restrict__ qkv, __half* __restrict__ o)
{
    extern __shared__ __half T[];
    const uint32_t tb = smem_u32(T);

    const int t    = threadIdx.x;
    const int lane = t & 31;
    const int h    = t >> 5;
    const size_t tokBase = (size_t)blockIdx.x * 32;

    {
        const __half* src = qkv + tokBase * NQKV;
        #pragma unroll
        for (int i = 0; i < 24; i++) {
            int idx = i * 256 + t;
            int r = idx / 192, c = idx % 192;
            *(uint4*)(T + r * ROWH + c * 8) = *(const uint4*)(src + (size_t)r * NQKV + c * 8);
        }
    }
    __syncthreads();

    const uint32_t qOff = tb + h * 128;
    const uint32_t kOff = tb + 1024 + h * 128;
    const uint32_t vOff = tb + 2048 + h * 128;

    const int lr    = lane & 15;
    const int aKoff = (lane & 16) ? 16 : 0;
    const int bRow  = (lane & 7) + ((lane & 16) ? 8 : 0);
    const int bKoff = (lane & 8) ? 16 : 0;
    const int vCoff = (lane & 16) ? 16 : 0;

    float s[2][4][4];
    #pragma unroll
    for (int mt = 0; mt < 2; mt++)
        #pragma unroll
        for (int nt = 0; nt < 4; nt++)
            #pragma unroll
            for (int i = 0; i < 4; i++) s[mt][nt][i] = 0.f;

    #pragma unroll
    for (int kt = 0; kt < 4; kt++) {
        const int k0b = kt * 32;
        uint32_t a[2][4], b[2][4];
        #pragma unroll
        for (int mt = 0; mt < 2; mt++)
            ldsm4(a[mt], qOff + (mt * 16 + lr) * ROWB + k0b + aKoff);
        #pragma unroll
        for (int nb = 0; nb < 2; nb++)
            ldsm4(b[nb], kOff + (nb * 16 + bRow) * ROWB + k0b + bKoff);
        #pragma unroll
        for (int mt = 0; mt < 2; mt++)
            #pragma unroll
            for (int nb = 0; nb < 2; nb++) {
                mma_f16(s[mt][2 * nb    ], a[mt][0], a[mt][1], a[mt][2], a[mt][3],
                        b[nb][0], b[nb][1]);
                mma_f16(s[mt][2 * nb + 1], a[mt][0], a[mt][1], a[mt][2], a[mt][3],
                        b[nb][2], b[nb][3]);
            }
    }

    #pragma unroll
    for (int mt = 0; mt < 2; mt++)
        #pragma unroll
        for (int nt = 0; nt < 4; nt++)
            #pragma unroll
            for (int i = 0; i < 4; i++) s[mt][nt][i] *= ATT_SCALE;

    #pragma unroll
    for (int mt = 0; mt < 2; mt++) {
        float mA = -1e30f, mB = -1e30f;
        #pragma unroll
        for (int nt = 0; nt < 4; nt++) {
            mA = fmaxf(mA, fmaxf(s[mt][nt][0], s[mt][nt][1]));
            mB = fmaxf(mB, fmaxf(s[mt][nt][2], s[mt][nt][3]));
        }
        mA = fmaxf(mA, __shfl_xor_sync(~0u, mA, 1));
        mA = fmaxf(mA, __shfl_xor_sync(~0u, mA, 2));
        mB = fmaxf(mB, __shfl_xor_sync(~0u, mB, 1));
        mB = fmaxf(mB, __shfl_xor_sync(~0u, mB, 2));
        float sA = 0.f, sB = 0.f;
        #pragma unroll
        for (int nt = 0; nt < 4; nt++) {
            s[mt][nt][0] = __expf(s[mt][nt][0] - mA); sA += s[mt][nt][0];
            s[mt][nt][1] = __expf(s[mt][nt][1] - mA); sA += s[mt][nt][1];
            s[mt][nt][2] = __expf(s[mt][nt][2] - mB); sB += s[mt][nt][2];
            s[mt][nt][3] = __expf(s[mt][nt][3] - mB); sB += s[mt][nt][3];
        }
        sA += __shfl_xor_sync(~0u, sA, 1);
        sA += __shfl_xor_sync(~0u, sA, 2);
        sB += __shfl_xor_sync(~0u, sB, 1);
        sB += __shfl_xor_sync(~0u, sB, 2);
        float iA = 1.f / sA, iB = 1.f / sB;
        #pragma unroll
        for (int nt = 0; nt < 4; nt++) {
            s[mt][nt][0] *= iA; s[mt][nt][1] *= iA;
            s[mt][nt][2] *= iB; s[mt][nt][3] *= iB;
        }
    }

    uint32_t pk[2][2][4];
    #pragma unroll
    for (int mt = 0; mt < 2; mt++)
        #pragma unroll
        for (int kt = 0; kt < 2; kt++) {
            pk[mt][kt][0] = pack2h(s[mt][2 * kt    ][0], s[mt][2 * kt    ][1]);
            pk[mt][kt][1] = pack2h(s[mt][2 * kt    ][2], s[mt][2 * kt    ][3]);
            pk[mt][kt][2] = pack2h(s[mt][2 * kt + 1][0], s[mt][2 * kt + 1][1]);
            pk[mt][kt][3] = pack2h(s[mt][2 * kt + 1][2], s[mt][2 * kt + 1][3]);
        }

    float oa[2][8][4];
    #pragma unroll
    for (int mt = 0; mt < 2; mt++)
        #pragma unroll
        for (int nt = 0; nt < 8; nt++)
            #pragma unroll
            for (int i = 0; i < 4; i++) oa[mt][nt][i] = 0.f;

    #pragma unroll
    for (int kt = 0; kt < 2; kt++) {
        #pragma unroll
        for (int hf = 0; hf < 4; hf++) {
            uint32_t b[4];
            ldsm4t(b, vOff + (kt * 16 + lr) * ROWB + hf * 32 + vCoff);
            #pragma unroll
            for (int mt = 0; mt < 2; mt++) {
                mma_f16(oa[mt][2 * hf    ], pk[mt][kt][0], pk[mt][kt][1],
                        pk[mt][kt][2], pk[mt][kt][3], b[0], b[1]);
                mma_f16(oa[mt][2 * hf + 1], pk[mt][kt][0], pk[mt][kt][1],
                        pk[mt][kt][2], pk[mt][kt][3], b[2], b[3]);
            }
        }
    }

    __half* obase = o + tokBase * INNER + h * DH;
    #pragma unroll
    for (int mt = 0; mt < 2; mt++) {
        int row = mt * 16 + (lane >> 2);
        #pragma unroll
        for (int nt = 0; nt < 8; nt++) {
            int col = nt * 8 + 2 * (lane & 3);
            *(uint32_t*)(obase + (size_t)row * INNER + col) =
                pack2h(oa[mt][nt][0], oa[mt][nt][1]);
            *(uint32_t*)(obase + (size_t)(row + 8) * INNER + col) =
                pack2h(oa[mt][nt][2], oa[mt][nt][3]);
        }
    }
}

// ------------------------- launch -------------------------------------------

extern "C" void kernel_launch(void* const* d_in, const int* in_sizes, int n_in,
                              void* d_out, int out_size)
{
    const float* x     = (const float*)d_in[0];
    const float* W_qkv = (const float*)d_in[1];
    const float* W_out = (const float*)d_in[2];
    const float* b_out = (const float*)d_in[3];
    float* out = (float*)d_out;

    __half *xh, *qkv, *att, *wqT, *woT;
    cudaGetSymbolAddress((void**)&xh,  g_xh);
    cudaGetSymbolAddress((void**)&qkv, g_qkv);
    cudaGetSymbolAddress((void**)&att, g_attn);
    cudaGetSymbolAddress((void**)&wqT, g_WqkvT);
    cudaGetSymbolAddress((void**)&woT, g_WoutT);

    cudaFuncSetAttribute(gemm_h<__half>,
                         cudaFuncAttributeMaxDynamicSharedMemorySize, GSM_BYTES);
    cudaFuncSetAttribute(gemm_h<float>,
                         cudaFuncAttributeMaxDynamicSharedMemorySize, GSM_BYTES);
    cudaFuncSetAttribute(attn_core,
                         cudaFuncAttributeMaxDynamicSharedMemorySize, ASM_BYTES);

    const int n4 = TOKENS * DIMX / 4;
    f2h_kernel<<<n4 / 256, 256>>>(x, xh, n4);

    transpose_h<<<dim3(NQKV / 32, DIMX / 32), dim3(32, 8)>>>(W_qkv, wqT, DIMX, NQKV);
    transpose_h<<<dim3(DIMX / 32, INNER / 32), dim3(32, 8)>>>(W_out, woT, INNER, DIMX);

    // K1: qkv = xh @ W_qkv  (M=131072, K=256, N=1536), 12288 tiles persistent
    gemm_h<__half><<<GRIDSZ, 256, GSM_BYTES>>>(
        xh, wqT, qkv, DIMX, NQKV, NQKV / 128, (NQKV / 128) * (TOKENS / 128),
        nullptr);

    // K2: attention (one block per group)
    attn_core<<<GROUPS, 256, ASM_BYTES>>>(qkv, att);

    // K3: out = att @ W_out + b  (M=131072, K=512, N=256), 2048 tiles
    gemm_h<float><<<GRIDSZ, 256, GSM_BYTES>>>(
        att, woT, out, INNER, DIMX, DIMX / 128, (DIMX / 128) * (TOKENS / 128),
        b_out);
}

// round 14
// speedup vs baseline: 1.0927x; 1.0927x over previous
#include <cuda_runtime.h>
#include <cuda_fp16.h>
#include <cstdint>

// ---------------------------------------------------------------------------
// Attention_37074157699274 — round 14:
//  * K1 rebuilt weight-stationary: CTA = 128-row block, A staged once (full
//    K=256), B col-tiles (full K) double-buffered; 12 col tiles per CTA with
//    a barrier-free 256-mma straight-line inner loop per tile.
//  * K3 + attn: exact round-11 versions (proven best).
//   K0: x->fp16 ; T1/T2: weights -> [N,K] fp16
// ---------------------------------------------------------------------------

#define TOKENS   131072
#define GROUPS   4096
#define DIMX     256
#define NQKV     1536
#define INNER    512
#define HEADS    8
#define DH       64
#define ATT_SCALE 0.125f

__device__ __half g_xh  [(size_t)TOKENS * DIMX];
__device__ __half g_qkv [(size_t)TOKENS * NQKV];
__device__ __half g_attn[(size_t)TOKENS * INNER];
__device__ __half g_WqkvT[(size_t)NQKV * DIMX];
__device__ __half g_WoutT[(size_t)DIMX * INNER];

// ------------------------- helpers ------------------------------------------

__device__ __forceinline__ uint32_t pack2h(float x, float y) {
    __half2 h = __halves2half2(__float2half_rn(x), __float2half_rn(y));
    return *reinterpret_cast<uint32_t*>(&h);
}
__device__ __forceinline__ uint32_t smem_u32(const void* p) {
    uint32_t a;
    asm("{ .reg .u64 t; cvta.to.shared.u64 t, %1; cvt.u32.u64 %0, t; }"
        : "=r"(a) : "l"(p));
    return a;
}
__device__ __forceinline__ void cp16(uint32_t saddr, const void* gptr) {
    asm volatile("cp.async.cg.shared.global [%0], [%1], 16;"
                 :: "r"(saddr), "l"(gptr) : "memory");
}
__device__ __forceinline__ void ldsm4(uint32_t r[4], uint32_t addr) {
    asm volatile("ldmatrix.sync.aligned.m8n8.x4.shared.b16 {%0,%1,%2,%3}, [%4];"
                 : "=r"(r[0]), "=r"(r[1]), "=r"(r[2]), "=r"(r[3]) : "r"(addr));
}
__device__ __forceinline__ void ldsm4t(uint32_t r[4], uint32_t addr) {
    asm volatile("ldmatrix.sync.aligned.m8n8.x4.trans.shared.b16 {%0,%1,%2,%3}, [%4];"
                 : "=r"(r[0]), "=r"(r[1]), "=r"(r[2]), "=r"(r[3]) : "r"(addr));
}
__device__ __forceinline__ void mma_f16(float c[4], uint32_t a0, uint32_t a1,
                                        uint32_t a2, uint32_t a3,
                                        uint32_t b0, uint32_t b1) {
    asm volatile(
        "mma.sync.aligned.m16n8k16.row.col.f32.f16.f16.f32 "
        "{%0,%1,%2,%3}, {%4,%5,%6,%7}, {%8,%9}, {%0,%1,%2,%3};\n"
        : "+f"(c[0]), "+f"(c[1]), "+f"(c[2]), "+f"(c[3])
        : "r"(a0), "r"(a1), "r"(a2), "r"(a3), "r"(b0), "r"(b1));
}

// ------------------------- K1: weight-stationary GEMM -----------------------
// qkv[M,1536] = xh[M,256] @ WqkvT[1536,256]^T. One CTA per 128-row block.
// smem: A[128x256] staged once + 2 x B[128x256] (col-tile double buffer).
// Rows padded to 264 halfs (528 B; 528 mod 128 = 16 -> conflict-free ldsm).
// Inner loop per col tile: 16 unrolled k-steps, NO barriers.

#define K1STRB  528
#define K1_TILE (128 * K1STRB)            // 67584 B
#define K1_SM   (3 * K1_TILE)             // 202752 B
#define K1_NT   12                        // 1536 / 128 col tiles

__global__ __launch_bounds__(256, 1)
void gemm_k1(const __half* __restrict__ A, const __half* __restrict__ Bt,
             __half* __restrict__ C)
{
    extern __shared__ __half sh[];
    const uint32_t sb = smem_u32(sh);

    const int t     = threadIdx.x;
    const int lane  = t & 31;
    const int warp  = t >> 5;
    const int warpM = warp & 1;           // rows [warpM*64, +64)
    const int warpN = warp >> 1;          // cols [warpN*32, +32)

    const size_t rowBase = (size_t)blockIdx.x * 128;
    const __half* Ag = A + rowBase * DIMX;

    // ---- stage A (full 128x256) ; geometry: 32 16B-granules per row
    #pragma unroll
    for (int i = 0; i < 16; i++) {
        int g = i * 256 + t, r = g >> 5, s = g & 31;
        cp16(sb + r * K1STRB + s * 16, Ag + (size_t)r * DIMX + s * 8);
    }
    // ---- stage B tile 0 (same commit group as A), then tile 1
    auto stageB = [&](int ct, int buf) {
        const __half* Bg = Bt + (size_t)(ct * 128) * DIMX;
        const uint32_t bD = sb + K1_TILE + buf * K1_TILE;
        #pragma unroll
        for (int i = 0; i < 16; i++) {
            int g = i * 256 + t, r = g >> 5, s = g & 31;
            cp16(bD + r * K1STRB + s * 16, Bg + (size_t)r * DIMX + s * 8);
        }
    };
    stageB(0, 0);
    asm volatile("cp.async.commit_group;" ::: "memory");
    stageB(1, 1);
    asm volatile("cp.async.commit_group;" ::: "memory");

    const int lr    = lane & 15;
    const int aKoff = (lane & 16) ? 16 : 0;
    const int bRow  = (lane & 7) + ((lane & 16) ? 8 : 0);
    const int bKoff = (lane & 8) ? 16 : 0;

    for (int ct = 0; ct < K1_NT; ct++) {
        if (ct < K1_NT - 1) asm volatile("cp.async.wait_group 1;" ::: "memory");
        else                asm volatile("cp.async.wait_group 0;" ::: "memory");
        __syncthreads();

        const uint32_t aB = sb;
        const uint32_t bB = sb + K1_TILE + (ct & 1) * K1_TILE;

        float acc[4][4][4];
        #pragma unroll
        for (int mt = 0; mt < 4; mt++)
            #pragma unroll
            for (int nt = 0; nt < 4; nt++)
                #pragma unroll
                for (int i = 0; i < 4; i++) acc[mt][nt][i] = 0.f;

        // ---- barrier-free full-K mainloop (16 k-steps)
        #pragma unroll
        for (int ks = 0; ks < 16; ks++) {
            const int k0b = ks * 32;
            uint32_t a[4][4], b[2][4];
            #pragma unroll
            for (int mt = 0; mt < 4; mt++)
                ldsm4(a[mt], aB + (warpM * 64 + mt * 16 + lr) * K1STRB + k0b + aKoff);
            #pragma unroll
            for (int np = 0; np < 2; np++)
                ldsm4(b[np], bB + (warpN * 32 + np * 16 + bRow) * K1STRB + k0b + bKoff);
            #pragma unroll
            for (int nt = 0; nt < 4; nt++) {
                uint32_t b0 = b[nt >> 1][(nt & 1) * 2];
                uint32_t b1 = b[nt >> 1][(nt & 1) * 2 + 1];
                #pragma unroll
                for (int mt = 0; mt < 4; mt++)
                    mma_f16(acc[mt][nt], a[mt][0], a[mt][1], a[mt][2], a[mt][3],
                            b0, b1);
            }
        }
        __syncthreads();                   // reads of buf (ct&1) complete

        if (ct + 2 < K1_NT) {              // restage this buffer for ct+2
            stageB(ct + 2, ct & 1);
            asm volatile("cp.async.commit_group;" ::: "memory");
        }

        // ---- epilogue for this col tile
        const int colBase = ct * 128;
        #pragma unroll
        for (int mt = 0; mt < 4; mt++) {
            size_t row = rowBase + warpM * 64 + mt * 16 + (lane >> 2);
            #pragma unroll
            for (int nt = 0; nt < 4; nt++) {
                int col = colBase + warpN * 32 + nt * 8 + 2 * (lane & 3);
                *(uint32_t*)(C + row * NQKV + col) =
                    pack2h(acc[mt][nt][0], acc[mt][nt][1]);
                *(uint32_t*)(C + (row + 8) * NQKV + col) =
                    pack2h(acc[mt][nt][2], acc[mt][nt][3]);
            }
        }
    }
}

// ------------------------- K3 GEMM (round-11 proven, chunked) ---------------
// C[M,N] = A[M,K] @ Bt[N,K]^T + bias. CTA 128x128, K-chunk 64, 3-stage ring.

#define STRB   144
#define A_BYTES (128 * STRB)
#define B_BYTES (128 * STRB)
#define STG_BYTES (A_BYTES + B_BYTES)
#define NSTG   3
#define GSM_BYTES (NSTG * STG_BYTES)      // 110592

__global__ __launch_bounds__(256, 2)
void gemm_h(const __half* __restrict__ A, const __half* __restrict__ Bt,
            float* __restrict__ C, int K, int N, const float* __restrict__ bias)
{
    extern __shared__ __half sh[];
    const uint32_t sb = smem_u32(sh);

    const int t     = threadIdx.x;
    const int lane  = t & 31;
    const int warp  = t >> 5;
    const int warpM = warp & 1;
    const int warpN = warp >> 1;

    const size_t rowBase = (size_t)blockIdx.y * 128;
    const int    colBase = blockIdx.x * 128;
    const int NC = K >> 6;

    float acc[4][4][4];
    #pragma unroll
    for (int mt = 0; mt < 4; mt++)
        #pragma unroll
        for (int nt = 0; nt < 4; nt++)
            #pragma unroll
            for (int i = 0; i < 4; i++) acc[mt][nt][i] = 0.f;

    const __half* Ab = A  + rowBase * K;
    const __half* Bb = Bt + (size_t)colBase * K;

    auto stage = [&](int kc) {
        const int slot = kc % NSTG;
        const uint32_t aD = sb + slot * STG_BYTES;
        const uint32_t bD = aD + A_BYTES;
        const __half* As = Ab + kc * 64;
        const __half* Bs = Bb + kc * 64;
        #pragma unroll
        for (int i = 0; i < 4; i++) {
            int g = i * 256 + t, r = g >> 3, s = g & 7;
            cp16(aD + r * STRB + s * 16, As + (size_t)r * K + s * 8);
        }
        #pragma unroll
        for (int i = 0; i < 4; i++) {
            int g = i * 256 + t, r = g >> 3, s = g & 7;
            cp16(bD + r * STRB + s * 16, Bs + (size_t)r * K + s * 8);
        }
        asm volatile("cp.async.commit_group;" ::: "memory");
    };

    stage(0); stage(1);

    const int lr    = lane & 15;
    const int aKoff = (lane & 16) ? 16 : 0;
    const int bRow  = (lane & 7) + ((lane & 16) ? 8 : 0);
    const int bKoff = (lane & 8) ? 16 : 0;

    for (int kc = 0; kc < NC; kc++) {
        if (kc < NC - 1) asm volatile("cp.async.wait_group 1;" ::: "memory");
        else             asm volatile("cp.async.wait_group 0;" ::: "memory");
        __syncthreads();
        if (kc + 2 < NC) stage(kc + 2);

        const uint32_t aB = sb + (kc % NSTG) * STG_BYTES;
        const uint32_t bB = aB + A_BYTES;

        #pragma unroll
        for (int ks = 0; ks < 4; ks++) {
            const int k0b = ks * 32;
            uint32_t a[4][4], b[2][4];
            #pragma unroll
            for (int mt = 0; mt < 4; mt++)
                ldsm4(a[mt], aB + (warpM * 64 + mt * 16 + lr) * STRB + k0b + aKoff);
            #pragma unroll
            for (int np = 0; np < 2; np++)
                ldsm4(b[np], bB + (warpN * 32 + np * 16 + bRow) * STRB + k0b + bKoff);
            #pragma unroll
            for (int nt = 0; nt < 4; nt++) {
                uint32_t b0 = b[nt >> 1][(nt & 1) * 2];
                uint32_t b1 = b[nt >> 1][(nt & 1) * 2 + 1];
                #pragma unroll
                for (int mt = 0; mt < 4; mt++)
                    mma_f16(acc[mt][nt], a[mt][0], a[mt][1], a[mt][2], a[mt][3],
                            b0, b1);
            }
        }
    }

    #pragma unroll
    for (int mt = 0; mt < 4; mt++) {
        size_t row = rowBase + warpM * 64 + mt * 16 + (lane >> 2);
        #pragma unroll
        for (int nt = 0; nt < 4; nt++) {
            int col = colBase + warpN * 32 + nt * 8 + 2 * (lane & 3);
            float b0 = 0.f, b1 = 0.f;
            if (bias) { b0 = bias[col]; b1 = bias[col + 1]; }
            *(float2*)(C + row * N + col) =
                make_float2(acc[mt][nt][0] + b0, acc[mt][nt][1] + b1);
            *(float2*)(C + (row + 8) * N + col) =
                make_float2(acc[mt][nt][2] + b0, acc[mt][nt][3] + b1);
        }
    }
}

// ------------------------- aux kernels --------------------------------------

__global__ void f2h_kernel(const float* __restrict__ in, __half* __restrict__ out,
                           int n4)
{
    int i = blockIdx.x * blockDim.x + threadIdx.x;
    if (i < n4) {
        float4 v = ((const float4*)in)[i];
        ((uint2*)out)[i] = make_uint2(pack2h(v.x, v.y), pack2h(v.z, v.w));
    }
}

__global__ void transpose_h(const float* __restrict__ in, __half* __restrict__ out,
                            int R, int C)
{
    __shared__ float tile[32][33];
    int c0 = blockIdx.x * 32, r0 = blockIdx.y * 32;
    #pragma unroll
    for (int i = threadIdx.y; i < 32; i += 8)
        tile[i][threadIdx.x] = in[(size_t)(r0 + i) * C + c0 + threadIdx.x];
    __syncthreads();
    #pragma unroll
    for (int i = threadIdx.y; i < 32; i += 8)
        out[(size_t)(c0 + i) * R + r0 + threadIdx.x] =
            __float2half_rn(tile[threadIdx.x][i]);
}

// ------------------------- K2: attention, warp = head (round-11) ------------

#define ROWH 1544
#define ROWB (ROWH * 2)
#define ASM_BYTES (32 * ROWB)

__global__ __launch_bounds__(256)
void attn_core(const __half* __restrict__ qkv, __half* __restrict__ o)
{
    extern __shared__ __half T[];
    const uint32_t tb = smem_u32(T);

    const int t    = threadIdx.x;
    const int lane = t & 31;
    const int h    = t >> 5;
    const size_t tokBase = (size_t)blockIdx.x * 32;

    {
        const __half* src = qkv + tokBase * NQKV;
        #pragma unroll
        for (int i = 0; i < 24; i++) {
            int idx = i * 256 + t;
            int r = idx / 192, c = idx % 192;
            *(uint4*)(T + r * ROWH + c * 8) = *(const uint4*)(src + (size_t)r * NQKV + c * 8);
        }
    }
    __syncthreads();

    const uint32_t qOff = tb + h * 128;
    const uint32_t kOff = tb + 1024 + h * 128;
    const uint32_t vOff = tb + 2048 + h * 128;

    const int lr    = lane & 15;
    const int aKoff = (lane & 16) ? 16 : 0;
    const int bRow  = (lane & 7) + ((lane & 16) ? 8 : 0);
    const int bKoff = (lane & 8) ? 16 : 0;
    const int vCoff = (lane & 16) ? 16 : 0;

    float s[2][4][4];
    #pragma unroll
    for (int mt = 0; mt < 2; mt++)
        #pragma unroll
        for (int nt = 0; nt < 4; nt++)
            #pragma unroll
            for (int i = 0; i < 4; i++) s[mt][nt][i] = 0.f;

    #pragma unroll
    for (int kt = 0; kt < 4; kt++) {
        const int k0b = kt * 32;
        uint32_t a[2][4], b[2][4];
        #pragma unroll
        for (int mt = 0; mt < 2; mt++)
            ldsm4(a[mt], qOff + (mt * 16 + lr) * ROWB + k0b + aKoff);
        #pragma unroll
        for (int nb = 0; nb < 2; nb++)
            ldsm4(b[nb], kOff + (nb * 16 + bRow) * ROWB + k0b + bKoff);
        #pragma unroll
        for (int mt = 0; mt < 2; mt++)
            #pragma unroll
            for (int nb = 0; nb < 2; nb++) {
                mma_f16(s[mt][2 * nb    ], a[mt][0], a[mt][1], a[mt][2], a[mt][3],
                        b[nb][0], b[nb][1]);
                mma_f16(s[mt][2 * nb + 1], a[mt][0], a[mt][1], a[mt][2], a[mt][3],
                        b[nb][2], b[nb][3]);
            }
    }

    #pragma unroll
    for (int mt = 0; mt < 2; mt++)
        #pragma unroll
        for (int nt = 0; nt < 4; nt++)
            #pragma unroll
            for (int i = 0; i < 4; i++) s[mt][nt][i] *= ATT_SCALE;

    #pragma unroll
    for (int mt = 0; mt < 2; mt++) {
        float mA = -1e30f, mB = -1e30f;
        #pragma unroll
        for (int nt = 0; nt < 4; nt++) {
            mA = fmaxf(mA, fmaxf(s[mt][nt][0], s[mt][nt][1]));
            mB = fmaxf(mB, fmaxf(s[mt][nt][2], s[mt][nt][3]));
        }
        mA = fmaxf(mA, __shfl_xor_sync(~0u, mA, 1));
        mA = fmaxf(mA, __shfl_xor_sync(~0u, mA, 2));
        mB = fmaxf(mB, __shfl_xor_sync(~0u, mB, 1));
        mB = fmaxf(mB, __shfl_xor_sync(~0u, mB, 2));
        float sA = 0.f, sB = 0.f;
        #pragma unroll
        for (int nt = 0; nt < 4; nt++) {
            s[mt][nt][0] = __expf(s[mt][nt][0] - mA); sA += s[mt][nt][0];
            s[mt][nt][1] = __expf(s[mt][nt][1] - mA); sA += s[mt][nt][1];
            s[mt][nt][2] = __expf(s[mt][nt][2] - mB); sB += s[mt][nt][2];
            s[mt][nt][3] = __expf(s[mt][nt][3] - mB); sB += s[mt][nt][3];
        }
        sA += __shfl_xor_sync(~0u, sA, 1);
        sA += __shfl_xor_sync(~0u, sA, 2);
        sB += __shfl_xor_sync(~0u, sB, 1);
        sB += __shfl_xor_sync(~0u, sB, 2);
        float iA = 1.f / sA, iB = 1.f / sB;
        #pragma unroll
        for (int nt = 0; nt < 4; nt++) {
            s[mt][nt][0] *= iA; s[mt][nt][1] *= iA;
            s[mt][nt][2] *= iB; s[mt][nt][3] *= iB;
        }
    }

    uint32_t pk[2][2][4];
    #pragma unroll
    for (int mt = 0; mt < 2; mt++)
        #pragma unroll
        for (int kt = 0; kt < 2; kt++) {
            pk[mt][kt][0] = pack2h(s[mt][2 * kt    ][0], s[mt][2 * kt    ][1]);
            pk[mt][kt][1] = pack2h(s[mt][2 * kt    ][2], s[mt][2 * kt    ][3]);
            pk[mt][kt][2] = pack2h(s[mt][2 * kt + 1][0], s[mt][2 * kt + 1][1]);
            pk[mt][kt][3] = pack2h(s[mt][2 * kt + 1][2], s[mt][2 * kt + 1][3]);
        }

    float oa[2][8][4];
    #pragma unroll
    for (int mt = 0; mt < 2; mt++)
        #pragma unroll
        for (int nt = 0; nt < 8; nt++)
            #pragma unroll
            for (int i = 0; i < 4; i++) oa[mt][nt][i] = 0.f;

    #pragma unroll
    for (int kt = 0; kt < 2; kt++) {
        #pragma unroll
        for (int hf = 0; hf < 4; hf++) {
            uint32_t b[4];
            ldsm4t(b, vOff + (kt * 16 + lr) * ROWB + hf * 32 + vCoff);
            #pragma unroll
            for (int mt = 0; mt < 2; mt++) {
                mma_f16(oa[mt][2 * hf    ], pk[mt][kt][0], pk[mt][kt][1],
                        pk[mt][kt][2], pk[mt][kt][3], b[0], b[1]);
                mma_f16(oa[mt][2 * hf + 1], pk[mt][kt][0], pk[mt][kt][1],
                        pk[mt][kt][2], pk[mt][kt][3], b[2], b[3]);
            }
        }
    }

    __half* obase = o + tokBase * INNER + h * DH;
    #pragma unroll
    for (int mt = 0; mt < 2; mt++) {
        int row = mt * 16 + (lane >> 2);
        #pragma unroll
        for (int nt = 0; nt < 8; nt++) {
            int col = nt * 8 + 2 * (lane & 3);
            *(uint32_t*)(obase + (size_t)row * INNER + col) =
                pack2h(oa[mt][nt][0], oa[mt][nt][1]);
            *(uint32_t*)(obase + (size_t)(row + 8) * INNER + col) =
                pack2h(oa[mt][nt][2], oa[mt][nt][3]);
        }
    }
}

// ------------------------- launch -------------------------------------------

extern "C" void kernel_launch(void* const* d_in, const int* in_sizes, int n_in,
                              void* d_out, int out_size)
{
    const float* x     = (const float*)d_in[0];
    const float* W_qkv = (const float*)d_in[1];
    const float* W_out = (const float*)d_in[2];
    const float* b_out = (const float*)d_in[3];
    float* out = (float*)d_out;

    __half *xh, *qkv, *att, *wqT, *woT;
    cudaGetSymbolAddress((void**)&xh,  g_xh);
    cudaGetSymbolAddress((void**)&qkv, g_qkv);
    cudaGetSymbolAddress((void**)&att, g_attn);
    cudaGetSymbolAddress((void**)&wqT, g_WqkvT);
    cudaGetSymbolAddress((void**)&woT, g_WoutT);

    cudaFuncSetAttribute(gemm_k1,
                         cudaFuncAttributeMaxDynamicSharedMemorySize, K1_SM);
    cudaFuncSetAttribute(gemm_h,
                         cudaFuncAttributeMaxDynamicSharedMemorySize, GSM_BYTES);
    cudaFuncSetAttribute(attn_core,
                         cudaFuncAttributeMaxDynamicSharedMemorySize, ASM_BYTES);

    const int n4 = TOKENS * DIMX / 4;
    f2h_kernel<<<n4 / 256, 256>>>(x, xh, n4);

    transpose_h<<<dim3(NQKV / 32, DIMX / 32), dim3(32, 8)>>>(W_qkv, wqT, DIMX, NQKV);
    transpose_h<<<dim3(DIMX / 32, INNER / 32), dim3(32, 8)>>>(W_out, woT, INNER, DIMX);

    // K1: qkv = xh @ W_qkv  (weight-stationary, 1024 row-block CTAs)
    gemm_k1<<<TOKENS / 128, 256, K1_SM>>>(xh, wqT, qkv);

    // K2: attention (one block per group)
    attn_core<<<GROUPS, 256, ASM_BYTES>>>(qkv, att);

    // K3: out = att @ W_out + b  (M=131072, K=512, N=256)
    gemm_h<<<dim3(DIMX / 128, TOKENS / 128), 256, GSM_BYTES>>>(
        att, woT, out, INNER, DIMX, b_out);
}